// round 1
// baseline (speedup 1.0000x reference)
#include <cuda_runtime.h>
#include <cstdint>

// Problem constants
#define BT_   8192      // B*T
#define C_    1024
#define S_    4096      // kv entries
#define D_    256       // head dim
#define QH_   4
#define EPS_  1e-5f

// Scratch (static __device__ allocations are allowed)
__device__ float g_x[(size_t)BT_ * C_];   // 32 MB: LayerNorm output
__device__ float g_v[(size_t)S_ * D_];    //  4 MB: V matrix (w_proj^T reshaped)

// ---------------------------------------------------------------------------
// LayerNorm: one block per row of 1024
// ---------------------------------------------------------------------------
__global__ void __launch_bounds__(256) ln_kernel(const float* __restrict__ res,
                                                 const float* __restrict__ gam,
                                                 const float* __restrict__ bet) {
    const int row = blockIdx.x;
    const float* x = res + (size_t)row * C_;
    float* y = g_x + (size_t)row * C_;
    const int t = threadIdx.x;

    float v[4];
    float s = 0.f;
#pragma unroll
    for (int i = 0; i < 4; i++) { v[i] = x[t + 256 * i]; s += v[i]; }

    __shared__ float red[8];
    __shared__ float sh_mu, sh_rs;

#pragma unroll
    for (int o = 16; o; o >>= 1) s += __shfl_xor_sync(0xffffffffu, s, o);
    if ((t & 31) == 0) red[t >> 5] = s;
    __syncthreads();
    if (t == 0) {
        float tot = 0.f;
#pragma unroll
        for (int i = 0; i < 8; i++) tot += red[i];
        sh_mu = tot * (1.0f / (float)C_);
    }
    __syncthreads();
    const float mu = sh_mu;

    float s2 = 0.f;
#pragma unroll
    for (int i = 0; i < 4; i++) { float d = v[i] - mu; s2 += d * d; }
#pragma unroll
    for (int o = 16; o; o >>= 1) s2 += __shfl_xor_sync(0xffffffffu, s2, o);
    if ((t & 31) == 0) red[t >> 5] = s2;
    __syncthreads();
    if (t == 0) {
        float tot = 0.f;
#pragma unroll
        for (int i = 0; i < 8; i++) tot += red[i];
        sh_rs = rsqrtf(tot * (1.0f / (float)C_) + EPS_);
    }
    __syncthreads();
    const float rs = sh_rs;

#pragma unroll
    for (int i = 0; i < 4; i++) {
        int c = t + 256 * i;
        y[c] = (v[i] - mu) * rs * gam[c] + bet[c];
    }
}

// ---------------------------------------------------------------------------
// Build V[s][d] = w_proj[(s%4)*256 + d][s/4]   (i.e. w_proj^T.reshape(4096,256))
// ---------------------------------------------------------------------------
__global__ void __launch_bounds__(256) vt_kernel(const float* __restrict__ wproj) {
    int idx = blockIdx.x * 256 + threadIdx.x;     // 0 .. 1048575
    int s = idx >> 8;
    int d = idx & 255;
    g_v[idx] = wproj[(size_t)((s & 3) * 256 + d) * 1024 + (s >> 2)];
}

// ---------------------------------------------------------------------------
// Fused scores -> relu^2 -> out, per (32-row tile, head)
// ---------------------------------------------------------------------------
#define BM 32
#define TSS 64

__global__ void __launch_bounds__(256) fused_kernel(const float* __restrict__ res,
                                                    const float* __restrict__ wfc,
                                                    float* __restrict__ out) {
    extern __shared__ float smem[];
    float (*sQ)[260] = (float (*)[260])smem;                          // 32 x 260
    float (*sK)[68]  = (float (*)[68])(smem + 32 * 260);              // 64 x 68
    float (*sV)[256] = (float (*)[256])(smem + 32 * 260 + 64 * 68);   // 16 x 256
    float (*sP)[65]  = (float (*)[65])(smem + 32 * 260 + 64 * 68 + 16 * 256); // 32 x 65

    const int head = blockIdx.y;
    const int row0 = blockIdx.x * BM;
    const int t = threadIdx.x;

    const int rg = t >> 5;   // 0..7   (phase B row group; constant per warp)
    const int dg = t & 31;   // 0..31  (phase B d group)
    const int rr = t & 15;   // 0..15  (phase A row)
    const int sg = t >> 4;   // 0..15  (phase A s group)

    // Load Q tile (32 x 256), fully coalesced
#pragma unroll
    for (int k = 0; k < 8; k++) {
        int f4 = k * 256 + t;        // float4 index 0..2047
        int r  = f4 >> 6;
        int c  = (f4 & 63) << 2;
        *(float4*)&sQ[r][c] =
            *(const float4*)(g_x + (size_t)(row0 + r) * C_ + head * D_ + c);
    }

    float acc[4][8];
#pragma unroll
    for (int i = 0; i < 4; i++)
#pragma unroll
        for (int j = 0; j < 8; j++) acc[i][j] = 0.f;

    __syncthreads();

    for (int s0 = 0; s0 < S_; s0 += TSS) {
        // ---------------- Phase A: scores = Q . K^T ----------------
        float sc[2][4];
#pragma unroll
        for (int a = 0; a < 2; a++)
#pragma unroll
            for (int j = 0; j < 4; j++) sc[a][j] = 0.f;

        for (int dc = 0; dc < D_; dc += 64) {
            // load K chunk [64 s][64 d], coalesced
#pragma unroll
            for (int k = 0; k < 4; k++) {
                int f4 = k * 256 + t;     // 0..1023
                int s  = f4 >> 4;
                int c  = (f4 & 15) << 2;
                *(float4*)&sK[s][c] =
                    *(const float4*)(wfc + (size_t)(s0 + s) * D_ + dc + c);
            }
            __syncthreads();
#pragma unroll
            for (int d = 0; d < 64; d += 4) {
                float4 q0 = *(const float4*)&sQ[rr][dc + d];
                float4 q1 = *(const float4*)&sQ[rr + 16][dc + d];
#pragma unroll
                for (int j = 0; j < 4; j++) {
                    float4 kv = *(const float4*)&sK[sg * 4 + j][d];
                    sc[0][j] += q0.x * kv.x + q0.y * kv.y + q0.z * kv.z + q0.w * kv.w;
                    sc[1][j] += q1.x * kv.x + q1.y * kv.y + q1.z * kv.z + q1.w * kv.w;
                }
            }
            __syncthreads();
        }

        // P = relu(score)^2
#pragma unroll
        for (int j = 0; j < 4; j++) {
            float p0 = fmaxf(sc[0][j], 0.f);
            float p1 = fmaxf(sc[1][j], 0.f);
            sP[rr][sg * 4 + j]      = p0 * p0;
            sP[rr + 16][sg * 4 + j] = p1 * p1;
        }
        __syncthreads();

        // ---------------- Phase B: out += P . V ----------------
        for (int sc2 = 0; sc2 < TSS; sc2 += 16) {
            // load V chunk [16 s][256 d], coalesced
#pragma unroll
            for (int k = 0; k < 4; k++) {
                int f4 = k * 256 + t;     // 0..1023
                int s  = f4 >> 6;
                int c  = (f4 & 63) << 2;
                *(float4*)&sV[s][c] =
                    *(const float4*)(g_v + (size_t)(s0 + sc2 + s) * D_ + c);
            }
            __syncthreads();
#pragma unroll
            for (int s = 0; s < 16; s++) {
                float4 v0 = *(const float4*)&sV[s][dg * 4];          // d = 4*dg..
                float4 v1 = *(const float4*)&sV[s][128 + dg * 4];    // d = 128+4*dg..
#pragma unroll
                for (int i = 0; i < 4; i++) {
                    float p = sP[rg * 4 + i][sc2 + s];
                    acc[i][0] += p * v0.x; acc[i][1] += p * v0.y;
                    acc[i][2] += p * v0.z; acc[i][3] += p * v0.w;
                    acc[i][4] += p * v1.x; acc[i][5] += p * v1.y;
                    acc[i][6] += p * v1.z; acc[i][7] += p * v1.w;
                }
            }
            __syncthreads();
        }
    }

    // Epilogue: out = residual + acc
#pragma unroll
    for (int i = 0; i < 4; i++) {
        size_t base = (size_t)(row0 + rg * 4 + i) * C_ + head * D_;
        size_t b0 = base + dg * 4;
        size_t b1 = base + 128 + dg * 4;
        float4 r0 = *(const float4*)(res + b0);
        float4 r1 = *(const float4*)(res + b1);
        float4 o0 = make_float4(acc[i][0] + r0.x, acc[i][1] + r0.y,
                                acc[i][2] + r0.z, acc[i][3] + r0.w);
        float4 o1 = make_float4(acc[i][4] + r1.x, acc[i][5] + r1.y,
                                acc[i][6] + r1.z, acc[i][7] + r1.w);
        *(float4*)(out + b0) = o0;
        *(float4*)(out + b1) = o1;
    }
}

// ---------------------------------------------------------------------------
extern "C" void kernel_launch(void* const* d_in, const int* in_sizes, int n_in,
                              void* d_out, int out_size) {
    (void)in_sizes; (void)n_in; (void)out_size;
    const float* residual = (const float*)d_in[0];
    const float* w_fc     = (const float*)d_in[1];
    const float* w_proj   = (const float*)d_in[2];
    const float* ln_g     = (const float*)d_in[3];
    const float* ln_b     = (const float*)d_in[4];
    float* out = (float*)d_out;

    const int smem_bytes = (32 * 260 + 64 * 68 + 16 * 256 + 32 * 65) * (int)sizeof(float);
    cudaFuncSetAttribute(fused_kernel, cudaFuncAttributeMaxDynamicSharedMemorySize,
                         smem_bytes);

    ln_kernel<<<BT_, 256>>>(residual, ln_g, ln_b);
    vt_kernel<<<S_ * D_ / 256, 256>>>(w_proj);
    fused_kernel<<<dim3(BT_ / BM, QH_), 256, smem_bytes>>>(residual, w_fc, out);
}

// round 3
// speedup vs baseline: 2.8857x; 2.8857x over previous
#include <cuda_runtime.h>
#include <cuda_bf16.h>
#include <cstdint>

#define BT_   8192
#define C_    1024
#define S_    4096
#define QH_   4
#define EPS_  1e-5f

// ---------------- scratch ----------------
__device__ __nv_bfloat16 g_q[(size_t)BT_ * 2048];   // 32MB [row][h*512 + (hi|lo)*256 + d]
__device__ __nv_bfloat16 g_k[(size_t)S_ * 512];     //  4MB [s][(hi|lo)*256 + d]
__device__ __nv_bfloat16 g_vt[2ull * 256 * S_];     //  4MB [hilo][d][s]

// ---------------- helpers ----------------
__device__ __forceinline__ uint32_t smem_u32(const void* p) {
    uint32_t a;
    asm("{ .reg .u64 t; cvta.to.shared.u64 t, %1; cvt.u32.u64 %0, t; }" : "=r"(a) : "l"(p));
    return a;
}
__device__ __forceinline__ void ldsm4(uint32_t* r, uint32_t addr) {
    asm volatile("ldmatrix.sync.aligned.m8n8.x4.shared.b16 {%0,%1,%2,%3}, [%4];"
                 : "=r"(r[0]), "=r"(r[1]), "=r"(r[2]), "=r"(r[3]) : "r"(addr));
}
__device__ __forceinline__ void mma16816(float* c, const uint32_t* a, const uint32_t* b) {
    asm volatile("mma.sync.aligned.m16n8k16.row.col.f32.bf16.bf16.f32 "
                 "{%0,%1,%2,%3}, {%4,%5,%6,%7}, {%8,%9}, {%0,%1,%2,%3};"
                 : "+f"(c[0]), "+f"(c[1]), "+f"(c[2]), "+f"(c[3])
                 : "r"(a[0]), "r"(a[1]), "r"(a[2]), "r"(a[3]), "r"(b[0]), "r"(b[1]));
}
// pack (f0 -> low half, f1 -> high half)
__device__ __forceinline__ uint32_t pack_bf2(float f0, float f1) {
    uint32_t d;
    asm("cvt.rn.bf16x2.f32 %0, %1, %2;" : "=r"(d) : "f"(f1), "f"(f0));
    return d;
}
__device__ __forceinline__ void bf16_split(float v, __nv_bfloat16& hi, __nv_bfloat16& lo) {
    hi = __float2bfloat16(v);
    lo = __float2bfloat16(v - __bfloat162float(hi));
}

// ---------------------------------------------------------------------------
// LayerNorm + bf16 split -> g_q
// ---------------------------------------------------------------------------
__global__ void __launch_bounds__(256) ln_kernel(const float* __restrict__ res,
                                                 const float* __restrict__ gam,
                                                 const float* __restrict__ bet) {
    const int row = blockIdx.x;
    const float* x = res + (size_t)row * C_;
    const int t = threadIdx.x;

    float v[4];
    float s = 0.f;
#pragma unroll
    for (int i = 0; i < 4; i++) { v[i] = x[t + 256 * i]; s += v[i]; }

    __shared__ float red[8];
    __shared__ float sh_mu, sh_rs;
#pragma unroll
    for (int o = 16; o; o >>= 1) s += __shfl_xor_sync(0xffffffffu, s, o);
    if ((t & 31) == 0) red[t >> 5] = s;
    __syncthreads();
    if (t == 0) {
        float tot = 0.f;
#pragma unroll
        for (int i = 0; i < 8; i++) tot += red[i];
        sh_mu = tot * (1.0f / (float)C_);
    }
    __syncthreads();
    const float mu = sh_mu;
    float s2 = 0.f;
#pragma unroll
    for (int i = 0; i < 4; i++) { float d = v[i] - mu; s2 += d * d; }
#pragma unroll
    for (int o = 16; o; o >>= 1) s2 += __shfl_xor_sync(0xffffffffu, s2, o);
    if ((t & 31) == 0) red[t >> 5] = s2;
    __syncthreads();
    if (t == 0) {
        float tot = 0.f;
#pragma unroll
        for (int i = 0; i < 8; i++) tot += red[i];
        sh_rs = rsqrtf(tot * (1.0f / (float)C_) + EPS_);
    }
    __syncthreads();
    const float rs = sh_rs;

#pragma unroll
    for (int i = 0; i < 4; i++) {
        int c = t + 256 * i;
        float y = (v[i] - mu) * rs * gam[c] + bet[c];
        int h = c >> 8, d = c & 255;
        __nv_bfloat16 hi, lo;
        bf16_split(y, hi, lo);
        size_t base = (size_t)row * 2048 + h * 512 + d;
        g_q[base] = hi;
        g_q[base + 256] = lo;
    }
}

__global__ void __launch_bounds__(256) kext_kernel(const float* __restrict__ wfc) {
    int idx = blockIdx.x * 256 + threadIdx.x;
    float v = wfc[idx];
    int s = idx >> 8, d = idx & 255;
    __nv_bfloat16 hi, lo;
    bf16_split(v, hi, lo);
    g_k[(size_t)s * 512 + d] = hi;
    g_k[(size_t)s * 512 + 256 + d] = lo;
}

__global__ void __launch_bounds__(256) vext_kernel(const float* __restrict__ wproj) {
    int idx = blockIdx.x * 256 + threadIdx.x;
    float v = wproj[idx];
    int r = idx >> 10, cc = idx & 1023;
    int d = r & 255;
    int s = cc * 4 + (r >> 8);
    __nv_bfloat16 hi, lo;
    bf16_split(v, hi, lo);
    g_vt[(size_t)d * 4096 + s] = hi;
    g_vt[1048576ull + (size_t)d * 4096 + s] = lo;
}

// ---------------------------------------------------------------------------
// Fused kernel: CTA = 128 rows x 1 head; warps = 16 rows each; S-chunks of 64
// SMEM: Q [128][520] bf16 (hi|lo along k), KV shared buffer:
//   GEMM1 phase: K [64][520] bf16
//   GEMM2 phase: V^T hi [256][72] + lo [256][72]
// ---------------------------------------------------------------------------
#define SQ_OFF   0
#define SQ_STR   520
#define SKV_OFF  133120
#define SK_STR   520
#define SV_STR   72
#define SV_LO    36864
#define SMEM_TOT 206848

__global__ void __launch_bounds__(256, 1) fused_kernel(const float* __restrict__ res,
                                                       float* __restrict__ out) {
    extern __shared__ char smem[];
    const uint32_t sb = smem_u32(smem);

    const int t = threadIdx.x;
    const int lane = t & 31;
    const int wid = t >> 5;
    const int m0 = wid * 16;
    const int head = blockIdx.y;
    const int row0 = blockIdx.x * 128;

    // ---- load Q tile: rows row0..row0+127, k 0..511 (hi|lo) ----
    {
        const __nv_bfloat16* qsrc = g_q + (size_t)row0 * 2048 + head * 512;
#pragma unroll
        for (int i = 0; i < 32; i++) {
            int idx = i * 256 + t;
            int m = idx >> 6, c = idx & 63;
            uint4 v = *(const uint4*)(qsrc + (size_t)m * 2048 + c * 8);
            *(uint4*)(smem + SQ_OFF + m * (SQ_STR * 2) + c * 16) = v;
        }
    }

    // O accumulators: 32 n-tiles (d), 4 f32 each
    float c2[32][4];
#pragma unroll
    for (int i = 0; i < 32; i++)
#pragma unroll
        for (int j = 0; j < 4; j++) c2[i][j] = 0.f;

    // precomputed ldmatrix lane addressing
    const uint32_t qa_base = sb + SQ_OFF +
        (uint32_t)(((m0 + (lane & 15)) * SQ_STR + (lane >> 4) * 8) * 2);
    const int brow = (lane & 7) + ((lane >> 4) << 3);
    const int bc8 = ((lane >> 3) & 1) << 3;
    const uint32_t kb_base = sb + SKV_OFF + (uint32_t)((brow * SK_STR + bc8) * 2);
    const uint32_t vb_base = sb + SKV_OFF + (uint32_t)((brow * SV_STR + bc8) * 2);

    for (int it = 0; it < 64; it++) {
        const int s0 = it * 64;
        __syncthreads();   // previous GEMM2 done reading V buffer

        // ---- load K chunk [64][512] ----
        {
            const __nv_bfloat16* ksrc = g_k + (size_t)s0 * 512;
#pragma unroll
            for (int i = 0; i < 16; i++) {
                int idx = i * 256 + t;
                int s = idx >> 6, c = idx & 63;
                uint4 v = *(const uint4*)(ksrc + (size_t)s * 512 + c * 8);
                *(uint4*)(smem + SKV_OFF + s * (SK_STR * 2) + c * 16) = v;
            }
        }
        __syncthreads();

        // ---- GEMM1: scores[16 x 64] per warp, 3 split terms ----
        float c1[8][4];
#pragma unroll
        for (int i = 0; i < 8; i++)
#pragma unroll
            for (int j = 0; j < 4; j++) c1[i][j] = 0.f;

#pragma unroll
        for (int term = 0; term < 3; term++) {
            const int aoff = (term == 2) ? 256 : 0;
            const int boff = (term == 1) ? 256 : 0;
#pragma unroll 4
            for (int ks = 0; ks < 16; ks++) {
                uint32_t a[4];
                ldsm4(a, qa_base + (uint32_t)((aoff + ks * 16) * 2));
#pragma unroll
                for (int ntp = 0; ntp < 4; ntp++) {
                    uint32_t b[4];
                    ldsm4(b, kb_base +
                          (uint32_t)((ntp * 16 * SK_STR + boff + ks * 16) * 2));
                    mma16816(c1[ntp * 2], a, b);
                    mma16816(c1[ntp * 2 + 1], a, b + 2);
                }
            }
        }

        // ---- relu^2 + bf16 split -> GEMM2 A fragments (register-only) ----
        uint32_t aH[4][4], aL[4][4];
#pragma unroll
        for (int j = 0; j < 4; j++) {          // k-step j covers score tiles 2j,2j+1
#pragma unroll
            for (int h = 0; h < 4; h++) {      // h: which a-reg
                const int nt = 2 * j + (h >> 1);
                const int base = (h & 1) * 2;  // 0 -> c[0],c[1]; 1 -> c[2],c[3]
                float p0 = fmaxf(c1[nt][base], 0.f);
                float p1 = fmaxf(c1[nt][base + 1], 0.f);
                p0 *= p0; p1 *= p1;
                uint32_t hh = pack_bf2(p0, p1);
                float h0 = __uint_as_float(hh << 16);
                float h1 = __uint_as_float(hh & 0xffff0000u);
                aH[j][h] = hh;
                aL[j][h] = pack_bf2(p0 - h0, p1 - h1);
            }
        }
        __syncthreads();   // all warps done reading K smem

        // ---- load V chunk: hi [256][64], lo [256][64] ----
        {
#pragma unroll
            for (int i = 0; i < 16; i++) {
                int idx = i * 256 + t;
                int hilo = idx >> 11;
                int rem = idx & 2047;
                int d = rem >> 3, c = rem & 7;
                uint4 v = *(const uint4*)(g_vt + (size_t)hilo * 1048576ull +
                                          (size_t)d * 4096 + s0 + c * 8);
                *(uint4*)(smem + SKV_OFF + hilo * SV_LO + d * (SV_STR * 2) + c * 16) = v;
            }
        }
        __syncthreads();

        // ---- GEMM2: O[16 x 256] += P . V^T (3 split terms) ----
#pragma unroll 1
        for (int ks = 0; ks < 4; ks++) {
#pragma unroll
            for (int ntp = 0; ntp < 16; ntp++) {
                uint32_t bh[4], bl[4];
                uint32_t ba = vb_base + (uint32_t)((ntp * 16 * SV_STR + ks * 16) * 2);
                ldsm4(bh, ba);
                ldsm4(bl, ba + SV_LO);
                const int nt = ntp * 2;
                mma16816(c2[nt],     aH[ks], bh);
                mma16816(c2[nt + 1], aH[ks], bh + 2);
                mma16816(c2[nt],     aH[ks], bl);
                mma16816(c2[nt + 1], aH[ks], bl + 2);
                mma16816(c2[nt],     aL[ks], bh);
                mma16816(c2[nt + 1], aL[ks], bh + 2);
            }
        }
    }

    // ---- epilogue: O + residual -> out ----
    {
        const int r0 = row0 + m0 + (lane >> 2);
        const int r1 = r0 + 8;
        const int cb = (lane & 3) * 2;
        const float* rs0 = res + (size_t)r0 * C_ + head * 256;
        const float* rs1 = res + (size_t)r1 * C_ + head * 256;
        float* o0 = out + (size_t)r0 * C_ + head * 256;
        float* o1 = out + (size_t)r1 * C_ + head * 256;
#pragma unroll
        for (int nt = 0; nt < 32; nt++) {
            const int c = nt * 8 + cb;
            float2 a = *(const float2*)(rs0 + c);
            float2 b = *(const float2*)(rs1 + c);
            float2 u = make_float2(c2[nt][0] + a.x, c2[nt][1] + a.y);
            float2 w = make_float2(c2[nt][2] + b.x, c2[nt][3] + b.y);
            *(float2*)(o0 + c) = u;
            *(float2*)(o1 + c) = w;
        }
    }
}

// ---------------------------------------------------------------------------
extern "C" void kernel_launch(void* const* d_in, const int* in_sizes, int n_in,
                              void* d_out, int out_size) {
    (void)in_sizes; (void)n_in; (void)out_size;
    const float* residual = (const float*)d_in[0];
    const float* w_fc     = (const float*)d_in[1];
    const float* w_proj   = (const float*)d_in[2];
    const float* ln_g     = (const float*)d_in[3];
    const float* ln_b     = (const float*)d_in[4];
    float* out = (float*)d_out;

    cudaFuncSetAttribute(fused_kernel, cudaFuncAttributeMaxDynamicSharedMemorySize,
                         SMEM_TOT);

    ln_kernel<<<BT_, 256>>>(residual, ln_g, ln_b);
    kext_kernel<<<4096, 256>>>(w_fc);
    vext_kernel<<<4096, 256>>>(w_proj);
    fused_kernel<<<dim3(64, QH_), 256, SMEM_TOT>>>(residual, out);
}

// round 4
// speedup vs baseline: 2.8899x; 1.0015x over previous
#include <cuda_runtime.h>
#include <cuda_bf16.h>
#include <cstdint>

#define BT_   8192
#define C_    1024
#define S_    4096
#define QH_   4
#define EPS_  1e-5f

// ---------------- scratch ----------------
__device__ __nv_bfloat16 g_q[(size_t)BT_ * 2048];   // 32MB [row][h*512 + (hi|lo)*256 + d]
__device__ __nv_bfloat16 g_k[(size_t)S_ * 512];     //  4MB [s][(hi|lo)*256 + d]
__device__ __nv_bfloat16 g_vt[2ull * 256 * S_];     //  4MB [hilo][d][s]

// ---------------- helpers ----------------
__device__ __forceinline__ uint32_t smem_u32(const void* p) {
    uint32_t a;
    asm("{ .reg .u64 t; cvta.to.shared.u64 t, %1; cvt.u32.u64 %0, t; }" : "=r"(a) : "l"(p));
    return a;
}
__device__ __forceinline__ void ldsm4(uint32_t* r, uint32_t addr) {
    asm volatile("ldmatrix.sync.aligned.m8n8.x4.shared.b16 {%0,%1,%2,%3}, [%4];"
                 : "=r"(r[0]), "=r"(r[1]), "=r"(r[2]), "=r"(r[3]) : "r"(addr));
}
__device__ __forceinline__ void mma16816(float* c, const uint32_t* a, const uint32_t* b) {
    asm volatile("mma.sync.aligned.m16n8k16.row.col.f32.bf16.bf16.f32 "
                 "{%0,%1,%2,%3}, {%4,%5,%6,%7}, {%8,%9}, {%0,%1,%2,%3};"
                 : "+f"(c[0]), "+f"(c[1]), "+f"(c[2]), "+f"(c[3])
                 : "r"(a[0]), "r"(a[1]), "r"(a[2]), "r"(a[3]), "r"(b[0]), "r"(b[1]));
}
// pack (f0 -> low half, f1 -> high half)
__device__ __forceinline__ uint32_t pack_bf2(float f0, float f1) {
    uint32_t d;
    asm("cvt.rn.bf16x2.f32 %0, %1, %2;" : "=r"(d) : "f"(f1), "f"(f0));
    return d;
}
__device__ __forceinline__ void bf16_split(float v, __nv_bfloat16& hi, __nv_bfloat16& lo) {
    hi = __float2bfloat16(v);
    lo = __float2bfloat16(v - __bfloat162float(hi));
}

// ---------------------------------------------------------------------------
// LayerNorm + bf16 split -> g_q
// ---------------------------------------------------------------------------
__global__ void __launch_bounds__(256) ln_kernel(const float* __restrict__ res,
                                                 const float* __restrict__ gam,
                                                 const float* __restrict__ bet) {
    const int row = blockIdx.x;
    const float* x = res + (size_t)row * C_;
    const int t = threadIdx.x;

    float v[4];
    float s = 0.f;
#pragma unroll
    for (int i = 0; i < 4; i++) { v[i] = x[t + 256 * i]; s += v[i]; }

    __shared__ float red[8];
    __shared__ float sh_mu, sh_rs;
#pragma unroll
    for (int o = 16; o; o >>= 1) s += __shfl_xor_sync(0xffffffffu, s, o);
    if ((t & 31) == 0) red[t >> 5] = s;
    __syncthreads();
    if (t == 0) {
        float tot = 0.f;
#pragma unroll
        for (int i = 0; i < 8; i++) tot += red[i];
        sh_mu = tot * (1.0f / (float)C_);
    }
    __syncthreads();
    const float mu = sh_mu;
    float s2 = 0.f;
#pragma unroll
    for (int i = 0; i < 4; i++) { float d = v[i] - mu; s2 += d * d; }
#pragma unroll
    for (int o = 16; o; o >>= 1) s2 += __shfl_xor_sync(0xffffffffu, s2, o);
    if ((t & 31) == 0) red[t >> 5] = s2;
    __syncthreads();
    if (t == 0) {
        float tot = 0.f;
#pragma unroll
        for (int i = 0; i < 8; i++) tot += red[i];
        sh_rs = rsqrtf(tot * (1.0f / (float)C_) + EPS_);
    }
    __syncthreads();
    const float rs = sh_rs;

#pragma unroll
    for (int i = 0; i < 4; i++) {
        int c = t + 256 * i;
        float y = (v[i] - mu) * rs * gam[c] + bet[c];
        int h = c >> 8, d = c & 255;
        __nv_bfloat16 hi, lo;
        bf16_split(y, hi, lo);
        size_t base = (size_t)row * 2048 + h * 512 + d;
        g_q[base] = hi;
        g_q[base + 256] = lo;
    }
}

__global__ void __launch_bounds__(256) kext_kernel(const float* __restrict__ wfc) {
    int idx = blockIdx.x * 256 + threadIdx.x;
    float v = wfc[idx];
    int s = idx >> 8, d = idx & 255;
    __nv_bfloat16 hi, lo;
    bf16_split(v, hi, lo);
    g_k[(size_t)s * 512 + d] = hi;
    g_k[(size_t)s * 512 + 256 + d] = lo;
}

__global__ void __launch_bounds__(256) vext_kernel(const float* __restrict__ wproj) {
    int idx = blockIdx.x * 256 + threadIdx.x;
    float v = wproj[idx];
    int r = idx >> 10, cc = idx & 1023;
    int d = r & 255;
    int s = cc * 4 + (r >> 8);
    __nv_bfloat16 hi, lo;
    bf16_split(v, hi, lo);
    g_vt[(size_t)d * 4096 + s] = hi;
    g_vt[1048576ull + (size_t)d * 4096 + s] = lo;
}

// ---------------------------------------------------------------------------
// Fused kernel: CTA = 128 rows x 1 head; warps = 16 rows each; S-chunks of 64
// SMEM: Q [128][520] bf16 (hi|lo along k), KV shared buffer:
//   GEMM1 phase: K [64][520] bf16
//   GEMM2 phase: V^T hi [256][72] + lo [256][72]
// ---------------------------------------------------------------------------
#define SQ_OFF   0
#define SQ_STR   520
#define SKV_OFF  133120
#define SK_STR   520
#define SV_STR   72
#define SV_LO    36864
#define SMEM_TOT 206848

__global__ void __launch_bounds__(256, 1) fused_kernel(const float* __restrict__ res,
                                                       float* __restrict__ out) {
    extern __shared__ char smem[];
    const uint32_t sb = smem_u32(smem);

    const int t = threadIdx.x;
    const int lane = t & 31;
    const int wid = t >> 5;
    const int m0 = wid * 16;
    const int head = blockIdx.y;
    const int row0 = blockIdx.x * 128;

    // ---- load Q tile: rows row0..row0+127, k 0..511 (hi|lo) ----
    {
        const __nv_bfloat16* qsrc = g_q + (size_t)row0 * 2048 + head * 512;
#pragma unroll
        for (int i = 0; i < 32; i++) {
            int idx = i * 256 + t;
            int m = idx >> 6, c = idx & 63;
            uint4 v = *(const uint4*)(qsrc + (size_t)m * 2048 + c * 8);
            *(uint4*)(smem + SQ_OFF + m * (SQ_STR * 2) + c * 16) = v;
        }
    }

    // O accumulators: 32 n-tiles (d), 4 f32 each
    float c2[32][4];
#pragma unroll
    for (int i = 0; i < 32; i++)
#pragma unroll
        for (int j = 0; j < 4; j++) c2[i][j] = 0.f;

    // precomputed ldmatrix lane addressing
    const uint32_t qa_base = sb + SQ_OFF +
        (uint32_t)(((m0 + (lane & 15)) * SQ_STR + (lane >> 4) * 8) * 2);
    const int brow = (lane & 7) + ((lane >> 4) << 3);
    const int bc8 = ((lane >> 3) & 1) << 3;
    const uint32_t kb_base = sb + SKV_OFF + (uint32_t)((brow * SK_STR + bc8) * 2);
    const uint32_t vb_base = sb + SKV_OFF + (uint32_t)((brow * SV_STR + bc8) * 2);

    for (int it = 0; it < 64; it++) {
        const int s0 = it * 64;
        __syncthreads();   // previous GEMM2 done reading V buffer

        // ---- load K chunk [64][512] ----
        {
            const __nv_bfloat16* ksrc = g_k + (size_t)s0 * 512;
#pragma unroll
            for (int i = 0; i < 16; i++) {
                int idx = i * 256 + t;
                int s = idx >> 6, c = idx & 63;
                uint4 v = *(const uint4*)(ksrc + (size_t)s * 512 + c * 8);
                *(uint4*)(smem + SKV_OFF + s * (SK_STR * 2) + c * 16) = v;
            }
        }
        __syncthreads();

        // ---- GEMM1: scores[16 x 64] per warp, 3 split terms ----
        float c1[8][4];
#pragma unroll
        for (int i = 0; i < 8; i++)
#pragma unroll
            for (int j = 0; j < 4; j++) c1[i][j] = 0.f;

#pragma unroll
        for (int term = 0; term < 3; term++) {
            const int aoff = (term == 2) ? 256 : 0;
            const int boff = (term == 1) ? 256 : 0;
#pragma unroll 4
            for (int ks = 0; ks < 16; ks++) {
                uint32_t a[4];
                ldsm4(a, qa_base + (uint32_t)((aoff + ks * 16) * 2));
#pragma unroll
                for (int ntp = 0; ntp < 4; ntp++) {
                    uint32_t b[4];
                    ldsm4(b, kb_base +
                          (uint32_t)((ntp * 16 * SK_STR + boff + ks * 16) * 2));
                    mma16816(c1[ntp * 2], a, b);
                    mma16816(c1[ntp * 2 + 1], a, b + 2);
                }
            }
        }

        // ---- relu^2 + bf16 split -> GEMM2 A fragments (register-only) ----
        uint32_t aH[4][4], aL[4][4];
#pragma unroll
        for (int j = 0; j < 4; j++) {          // k-step j covers score tiles 2j,2j+1
#pragma unroll
            for (int h = 0; h < 4; h++) {      // h: which a-reg
                const int nt = 2 * j + (h >> 1);
                const int base = (h & 1) * 2;  // 0 -> c[0],c[1]; 1 -> c[2],c[3]
                float p0 = fmaxf(c1[nt][base], 0.f);
                float p1 = fmaxf(c1[nt][base + 1], 0.f);
                p0 *= p0; p1 *= p1;
                uint32_t hh = pack_bf2(p0, p1);
                float h0 = __uint_as_float(hh << 16);
                float h1 = __uint_as_float(hh & 0xffff0000u);
                aH[j][h] = hh;
                aL[j][h] = pack_bf2(p0 - h0, p1 - h1);
            }
        }
        __syncthreads();   // all warps done reading K smem

        // ---- load V chunk: hi [256][64], lo [256][64] ----
        {
#pragma unroll
            for (int i = 0; i < 16; i++) {
                int idx = i * 256 + t;
                int hilo = idx >> 11;
                int rem = idx & 2047;
                int d = rem >> 3, c = rem & 7;
                uint4 v = *(const uint4*)(g_vt + (size_t)hilo * 1048576ull +
                                          (size_t)d * 4096 + s0 + c * 8);
                *(uint4*)(smem + SKV_OFF + hilo * SV_LO + d * (SV_STR * 2) + c * 16) = v;
            }
        }
        __syncthreads();

        // ---- GEMM2: O[16 x 256] += P . V^T (3 split terms) ----
#pragma unroll 1
        for (int ks = 0; ks < 4; ks++) {
#pragma unroll
            for (int ntp = 0; ntp < 16; ntp++) {
                uint32_t bh[4], bl[4];
                uint32_t ba = vb_base + (uint32_t)((ntp * 16 * SV_STR + ks * 16) * 2);
                ldsm4(bh, ba);
                ldsm4(bl, ba + SV_LO);
                const int nt = ntp * 2;
                mma16816(c2[nt],     aH[ks], bh);
                mma16816(c2[nt + 1], aH[ks], bh + 2);
                mma16816(c2[nt],     aH[ks], bl);
                mma16816(c2[nt + 1], aH[ks], bl + 2);
                mma16816(c2[nt],     aL[ks], bh);
                mma16816(c2[nt + 1], aL[ks], bh + 2);
            }
        }
    }

    // ---- epilogue: O + residual -> out ----
    {
        const int r0 = row0 + m0 + (lane >> 2);
        const int r1 = r0 + 8;
        const int cb = (lane & 3) * 2;
        const float* rs0 = res + (size_t)r0 * C_ + head * 256;
        const float* rs1 = res + (size_t)r1 * C_ + head * 256;
        float* o0 = out + (size_t)r0 * C_ + head * 256;
        float* o1 = out + (size_t)r1 * C_ + head * 256;
#pragma unroll
        for (int nt = 0; nt < 32; nt++) {
            const int c = nt * 8 + cb;
            float2 a = *(const float2*)(rs0 + c);
            float2 b = *(const float2*)(rs1 + c);
            float2 u = make_float2(c2[nt][0] + a.x, c2[nt][1] + a.y);
            float2 w = make_float2(c2[nt][2] + b.x, c2[nt][3] + b.y);
            *(float2*)(o0 + c) = u;
            *(float2*)(o1 + c) = w;
        }
    }
}

// ---------------------------------------------------------------------------
extern "C" void kernel_launch(void* const* d_in, const int* in_sizes, int n_in,
                              void* d_out, int out_size) {
    (void)in_sizes; (void)n_in; (void)out_size;
    const float* residual = (const float*)d_in[0];
    const float* w_fc     = (const float*)d_in[1];
    const float* w_proj   = (const float*)d_in[2];
    const float* ln_g     = (const float*)d_in[3];
    const float* ln_b     = (const float*)d_in[4];
    float* out = (float*)d_out;

    cudaFuncSetAttribute(fused_kernel, cudaFuncAttributeMaxDynamicSharedMemorySize,
                         SMEM_TOT);

    ln_kernel<<<BT_, 256>>>(residual, ln_g, ln_b);
    kext_kernel<<<4096, 256>>>(w_fc);
    vext_kernel<<<4096, 256>>>(w_proj);
    fused_kernel<<<dim3(64, QH_), 256, SMEM_TOT>>>(residual, out);
}